// round 16
// baseline (speedup 1.0000x reference)
#include <cuda_runtime.h>
#include <cuda_bf16.h>
#include <cstdint>

#define NGRID 8192
#define NLAYER 24
#define NPERIODS 50
#define NOBS 4096
#define NC 200
#define NPAD 64
#define KSPLIT 8
#define KB (NGRID / KSPLIT)      // 1024 K per job
#define KCHUNK 32
#define NCHUNK (KB / KCHUNK)     // 32
#define MT 64
#define NJOBS 512                // 64 m-tiles x 8 k-splits
#define NCTA 296                 // 148 SMs x 2 CTAs
#define NSTAGE 4
#define STAGE_A (MT * 128)           // 8192: 64 rows x 128B (32 f32)
#define STAGE_B (NPAD * 128)         // 8192: 64 rows x 128B (32 bf16 used)
#define STAGE (STAGE_A + STAGE_B)    // 16384
#define SMEM_TOT (NSTAGE * STAGE)    // 65536 -> 2 CTAs/SM
#define EROWS_PER_JOB 400            // 204800 / 512 (16 rows x 25 chunks)
#define VREF 3.0f
#define RAYF 0.92f

// ---------------- scratch (no allocation allowed) ----------------
__device__ __nv_bfloat16 g_Rt[NPAD * NGRID];    // [n=64][k=8192] bf16; rows 50..63 zero
__device__ float g_part[NOBS * KSPLIT * NPAD];  // [o][kz][p]
__device__ int g_cnt;                           // job counter (reset by k_dispersion)

// ---------------- helpers ----------------
__device__ __forceinline__ uint32_t smem_u32(const void* p) {
    uint32_t a;
    asm("{ .reg .u64 t; cvta.to.shared.u64 t, %1; cvt.u32.u64 %0, t; }" : "=r"(a) : "l"(p));
    return a;
}
#define CVTPK(r, lo, hi) asm("cvt.rn.satfinite.bf16x2.f32 %0, %1, %2;" : "=r"(r) : "f"(hi), "f"(lo))
#define LDSM4(r0, r1, r2, r3, a) \
    asm volatile("ldmatrix.sync.aligned.m8n8.x4.shared.b16 {%0,%1,%2,%3}, [%4];" \
        : "=r"(r0), "=r"(r1), "=r"(r2), "=r"(r3) : "r"(a))
#define MMA16816(c, a0, a1, a2, a3, b0, b1) \
    asm volatile("mma.sync.aligned.m16n8k16.row.col.f32.bf16.bf16.f32 " \
        "{%0,%1,%2,%3}, {%4,%5,%6,%7}, {%8,%9}, {%0,%1,%2,%3};" \
        : "+f"((c)[0]), "+f"((c)[1]), "+f"((c)[2]), "+f"((c)[3]) \
        : "r"(a0), "r"(a1), "r"(a2), "r"(a3), "r"(b0), "r"(b1))
#define CPA16(dst, src) asm volatile("cp.async.cg.shared.global [%0], [%1], 16;" :: "r"(dst), "l"(src) : "memory")
#define CPCOMMIT() asm volatile("cp.async.commit_group;" ::: "memory")
#define CPWAIT2()  asm volatile("cp.async.wait_group 2;" ::: "memory")

// ============ kernel 1: dispersion surrogate (R15 version) ============
__global__ __launch_bounds__(256) void k_dispersion(const float* __restrict__ Vs,
                                                    const float* __restrict__ thick,
                                                    const float* __restrict__ periods,
                                                    float* __restrict__ out) {
    __shared__ float w[NPERIODS][NLAYER];
    __shared__ float wsum[NPERIODS];
    __shared__ float zc[NLAYER];
    __shared__ float vsm[32 * 25];
    int tid = threadIdx.x;
    int g0 = blockIdx.x * 32;

    if (tid == 0) {
        float c = 0.0f;
        for (int l = 0; l < NLAYER; l++) {
            float t = thick[l];
            zc[l] = c + 0.5f * t;
            c += t;
        }
        if (blockIdx.x == 0) { out[0] = 0.0f; g_cnt = 0; }   // reset accum + job counter
    }
    __syncthreads();

    for (int idx = tid; idx < NPERIODS * NLAYER; idx += 256) {
        int p = idx / NLAYER, l = idx - p * NLAYER;
        float ds = VREF * periods[p] / 3.0f;
        w[p][l] = __expf(-zc[l] / ds) * thick[l];
    }
    for (int idx = tid; idx < 32 * NLAYER; idx += 256) {
        int gl = idx / NLAYER, l = idx - gl * NLAYER;
        vsm[gl * 25 + l] = Vs[(g0 + gl) * NLAYER + l];
    }
    __syncthreads();
    if (tid < NPERIODS) {
        float s = 0.0f;
#pragma unroll
        for (int l = 0; l < NLAYER; l++) s += w[tid][l];
        wsum[tid] = s;
    }
    __syncthreads();

    int gl = tid & 31, pg = tid >> 5;
    float vr[NLAYER];
#pragma unroll
    for (int l = 0; l < NLAYER; l++) vr[l] = vsm[gl * 25 + l];

#pragma unroll
    for (int blk = 0; blk < 2; blk++) {
        int p0 = pg + blk * 32;
        float d[4] = {0.0f, 0.0f, 0.0f, 0.0f};
#pragma unroll
        for (int l = 0; l < NLAYER; l++) {
            float x = vr[l];
            d[0] += w[(p0      ) < NPERIODS ? (p0      ) : 0][l] * x;
            d[1] += w[(p0 +  8) < NPERIODS ? (p0 +  8) : 0][l] * x;
            d[2] += w[(p0 + 16) < NPERIODS ? (p0 + 16) : 0][l] * x;
            d[3] += w[(p0 + 24) < NPERIODS ? (p0 + 24) : 0][l] * x;
        }
#pragma unroll
        for (int j = 0; j < 4; j++) {
            int p = p0 + j * 8;
            float val = (p < NPERIODS) ? wsum[p] / (RAYF * d[j]) : 0.0f;
            g_Rt[p * NGRID + g0 + gl] = __float2bfloat16(val);
        }
    }
}

// ============ kernel 2: persistent work-stealing GEMM + energy e_max stream ============
// grid 296 (2/SM on all 148 SMs). 512 jobs: job jb -> m-tile (jb&63)*64, k-slice (jb>>6)*1024.
// Each job also streams its 400 energy rows (16 per chunk, chunks 0..24).
__global__ __launch_bounds__(256, 2) void k_gemm(const float* __restrict__ A,
                                                 const float* __restrict__ energy,
                                                 float* __restrict__ out) {
    extern __shared__ __align__(128) char smem[];
    __shared__ float sred[8];
    __shared__ int sj;
    uint32_t sb = smem_u32(smem);
    int tid = threadIdx.x, lane = tid & 31, wid = tid >> 5;

    // ---- producer mappings (job-independent parts) ----
    int arow = tid >> 2;                 // A: row 0..63 (2 granules: cols 2c0, 2c0+1)
    int ac0 = (tid & 3) * 2;             // first 16B-granule col
    int bn = tid >> 2, bg = tid & 3;     // B: row 0..63, 16B granule 0..3
    uint32_t aXor = (uint32_t)((arow & 7) << 4);
    uint32_t dA0 = (uint32_t)(arow * 128) + (((uint32_t)(ac0    ) << 4) ^ aXor);
    uint32_t dA1 = (uint32_t)(arow * 128) + (((uint32_t)(ac0 + 1) << 4) ^ aXor);
    uint32_t dB = (uint32_t)(bn * 128) + (((uint32_t)bg << 4) ^ ((uint32_t)(bn & 7) << 4));

    // ---- consumer mappings ----
    int mw = wid & 3, nw = wid >> 2;     // warp = (m16 tile, n32 half)
    int gid = lane >> 2, tig = lane & 3;
    uint32_t rowA0 = (uint32_t)((mw * 16 + gid) * 128);
    uint32_t rowA1 = rowA0 + 8 * 128;
    uint32_t sub = (uint32_t)((tig & 1) * 8);
    int gbase = tig >> 1;
    int li = lane >> 3, lr = lane & 7;
    int b_nb = ((li >> 1) << 3) + lr;
    uint32_t lb_row = (uint32_t)(b_nb * 128);
    uint32_t lb_xor = (uint32_t)((b_nb & 7) << 4);
    uint32_t lb_kh = (uint32_t)((li & 1) * 16);
    uint32_t nwoff = (uint32_t)(nw * 4096);      // n32 half base in B buffer

    float msum = 0.0f;
    float4 er[2][2];

#pragma unroll 1
    for (;;) {
        // ---- steal a job ----
        if (tid == 0) sj = atomicAdd(&g_cnt, 1);
        __syncthreads();
        int jb = sj;
        if (jb >= NJOBS) break;

        int m0 = (jb & 63) * MT;
        int k0 = (jb >> 6) * KB;
        const float* srcA = A + (size_t)(m0 + arow) * NGRID + k0 + ac0 * 4;
        const __nv_bfloat16* srcB = g_Rt + (size_t)bn * NGRID + k0 + bg * 8;
        size_t ebase = (size_t)jb * EROWS_PER_JOB;

        float acc[4][4];
#pragma unroll
        for (int j = 0; j < 4; j++)
#pragma unroll
            for (int i = 0; i < 4; i++) acc[j][i] = 0.0f;

        auto issue = [&](int c) {
            uint32_t buf = sb + (uint32_t)(c & (NSTAGE - 1)) * STAGE;
            const float* sA = srcA + c * KCHUNK;
            CPA16(buf + dA0, sA);
            CPA16(buf + dA1, sA + 4);
            CPA16(buf + STAGE_A + dB, srcB + c * KCHUNK);
        };
        auto eload = [&](int c) {                // 2 rows per warp, chunks 0..24
            size_t r0 = ebase + (size_t)c * 16 + wid * 2;
#pragma unroll
            for (int j = 0; j < 2; j++) {
                const float4* e4 = (const float4*)(energy + (r0 + j) * NC);
                er[j][0] = e4[lane];
                er[j][1] = (lane < 18) ? e4[lane + 32]
                                       : make_float4(-1e30f, -1e30f, -1e30f, -1e30f);
            }
        };
        auto econsume = [&]() {
#pragma unroll
            for (int j = 0; j < 2; j++) {
                float4 a = er[j][0], b = er[j][1];
                float m = fmaxf(fmaxf(fmaxf(a.x, a.y), fmaxf(a.z, a.w)),
                                fmaxf(fmaxf(b.x, b.y), fmaxf(b.z, b.w)));
#pragma unroll
                for (int off = 16; off > 0; off >>= 1)
                    m = fmaxf(m, __shfl_xor_sync(0xffffffffu, m, off));
                msum += m;
            }
        };

#pragma unroll
        for (int s = 0; s < NSTAGE - 1; s++) { issue(s); CPCOMMIT(); }
        eload(0);

#pragma unroll 1
        for (int c = 0; c < NCHUNK; c++) {
            CPWAIT2();
            __syncthreads();
            if (c + NSTAGE - 1 < NCHUNK) issue(c + NSTAGE - 1);
            CPCOMMIT();

            if (c < 25) {
                econsume();
                if (c + 1 < 25) eload(c + 1);
            }

            uint32_t bufA = sb + (uint32_t)(c & (NSTAGE - 1)) * STAGE;
            uint32_t bufB = bufA + STAGE_A;
            const char* pA = smem + (size_t)(c & (NSTAGE - 1)) * STAGE;
#pragma unroll
            for (int ks = 0; ks < 2; ks++) {
                int gp0 = ks * 4 + gbase;
                uint32_t x0 = (uint32_t)((gp0 ^ gid) << 4);
                uint32_t x2 = (uint32_t)(((gp0 + 2) ^ gid) << 4);
                float2 v0 = *(const float2*)(pA + rowA0 + x0 + sub);
                float2 v1 = *(const float2*)(pA + rowA1 + x0 + sub);
                float2 v2 = *(const float2*)(pA + rowA0 + x2 + sub);
                float2 v3 = *(const float2*)(pA + rowA1 + x2 + sub);
                uint32_t a0, a1, a2, a3;
                CVTPK(a0, v0.x, v0.y);
                CVTPK(a1, v1.x, v1.y);
                CVTPK(a2, v2.x, v2.y);
                CVTPK(a3, v3.x, v3.y);
#pragma unroll
                for (int nt = 0; nt < 2; nt++) {
                    uint32_t b0, b1, b2, b3;
                    LDSM4(b0, b1, b2, b3,
                          bufB + nwoff + (uint32_t)(nt * 2048) + lb_row +
                          (((uint32_t)(ks * 32) + lb_kh) ^ lb_xor));
                    MMA16816(acc[2 * nt],     a0, a1, a2, a3, b0, b1);
                    MMA16816(acc[2 * nt + 1], a0, a1, a2, a3, b2, b3);
                }
            }
        }

        // ---- job epilogue: g_part[o][kz][p] ----
        int m = m0 + mw * 16 + gid;
        float* outp = g_part + (size_t)m * (KSPLIT * NPAD) + (jb >> 6) * NPAD + nw * 32;
#pragma unroll
        for (int j = 0; j < 4; j++) {
            *(float2*)(outp + j * 8 + tig * 2) = make_float2(acc[j][0], acc[j][1]);
            *(float2*)(outp + (size_t)8 * (KSPLIT * NPAD) + j * 8 + tig * 2) =
                make_float2(acc[j][2], acc[j][3]);
        }
    }

    // ---- CTA-level e_max reduction ----
    if (lane == 0) sred[wid] = msum;
    __syncthreads();
    if (tid == 0) {
        float t = 0.0f;
#pragma unroll
        for (int i = 0; i < 8; i++) t += sred[i];
        atomicAdd(out, -t);                      // -Σ e_max
    }
}

// ============ kernel 3: interp-only finalize (2 obs per block) ============
__global__ __launch_bounds__(128) void k_interp(const float* __restrict__ energy,
                                                const float* __restrict__ c_axis,
                                                float* __restrict__ out) {
    __shared__ float cs[2][NC];
    __shared__ float sred[4];
    int t = threadIdx.x;
    int grp = t >> 6, t64 = t & 63;
    int o = blockIdx.x * 2 + grp;

    for (int i = t64; i < NC; i += 64) cs[grp][i] = c_axis[(size_t)o * NC + i];
    float s = 0.0f;
    if (t64 < NPERIODS) {
        const float* pp = g_part + (size_t)o * (KSPLIT * NPAD) + t64;
#pragma unroll
        for (int kz = 0; kz < KSPLIT; kz++) s += pp[kz * NPAD];
    }
    __syncthreads();

    float contrib = 0.0f;
    if (t64 < NPERIODS) {
        float v = 1.0f / s;                  // c_pred
        int lo = 0, hi = NC;
        while (lo < hi) {
            int mid = (lo + hi) >> 1;
            if (cs[grp][mid] < v) lo = mid + 1; else hi = mid;
        }
        int idx = lo < 1 ? 1 : (lo > NC - 1 ? NC - 1 : lo);
        float c0 = cs[grp][idx - 1], c1 = cs[grp][idx];
        const float* e = energy + ((size_t)o * NPERIODS + t64) * NC;
        float e0 = e[idx - 1], e1 = e[idx];
        float wgt = (v - c0) / (c1 - c0 + 1e-12f);
        contrib = e0 + wgt * (e1 - e0);      // +e_interp
    }
#pragma unroll
    for (int off = 16; off > 0; off >>= 1)
        contrib += __shfl_xor_sync(0xffffffffu, contrib, off);
    if ((t & 31) == 0) sred[t >> 5] = contrib;
    __syncthreads();
    if (t == 0)
        atomicAdd(out, sred[0] + sred[1] + sred[2] + sred[3]);  // Σ e_interp
}

extern "C" void kernel_launch(void* const* d_in, const int* in_sizes, int n_in,
                              void* d_out, int out_size) {
    const float* Vs      = (const float*)d_in[0];
    const float* A       = (const float*)d_in[1];
    const float* energy  = (const float*)d_in[2];
    const float* c_axis  = (const float*)d_in[3];
    const float* thick   = (const float*)d_in[4];
    const float* periods = (const float*)d_in[5];
    float* out = (float*)d_out;

    cudaFuncSetAttribute(k_gemm, cudaFuncAttributeMaxDynamicSharedMemorySize, SMEM_TOT);

    k_dispersion<<<NGRID / 32, 256>>>(Vs, thick, periods, out);
    k_gemm<<<NCTA, 256, SMEM_TOT>>>(A, energy, out);
    k_interp<<<NOBS / 2, 128>>>(energy, c_axis, out);
}